// round 1
// baseline (speedup 1.0000x reference)
#include <cuda_runtime.h>
#include <math.h>

#define IMG   256
#define PSZ   16
#define PAD   8
#define WSZ   24      // scatter window per brush (covers full fp32-nonzero support)
#define NBR   64      // brushes per batch
#define CH    3
#define INV2S2 12.5f  // 1/(2*sigma^2), sigma=0.2
#define EPSV  1e-7f

__global__ void zero_out_kernel(float4* __restrict__ out, int n4) {
    int stride = gridDim.x * blockDim.x;
    for (int i = blockIdx.x * blockDim.x + threadIdx.x; i < n4; i += stride)
        out[i] = make_float4(0.f, 0.f, 0.f, 0.f);
}

__global__ __launch_bounds__(256) void brush_scatter_kernel(
    const float* __restrict__ brushes,   // [B, N, 2]
    const float* __restrict__ patches,   // [B, N, 3, 16, 16]
    float* __restrict__ out)             // [B, 3, 256, 256]  (h, w)
{
    __shared__ float patch_s[CH * PSZ * PSZ];   // 768
    __shared__ float denom_s[2 * PSZ];          // 32  (x then y)
    __shared__ float Fx_s[WSZ * PSZ];           // 384 (includes 1/N)
    __shared__ float Fy_s[WSZ * PSZ];           // 384
    __shared__ float t_s[CH * WSZ * PSZ];       // 1152

    const int bn  = blockIdx.x;
    const int b   = bn / NBR;
    const int tid = threadIdx.x;

    const float gx = brushes[bn * 2 + 0] * (float)IMG;
    const float gy = brushes[bn * 2 + 1] * (float)IMG;
    const int w0x = (int)floorf(gx) - 11;   // window start in w (image x)
    const int w0y = (int)floorf(gy) - 11;   // window start in h (image y)

    // --- load patch into smem ---
    const float* pbase = patches + (size_t)bn * (CH * PSZ * PSZ);
    for (int i = tid; i < CH * PSZ * PSZ; i += 256)
        patch_s[i] = pbase[i];

    // --- normalization denominators (over padded coord range, exact support) ---
    if (tid < 2 * PSZ) {
        const int   q  = tid & (PSZ - 1);
        const float g  = (tid < PSZ) ? gx : gy;
        const float mu = g + (float)q - 7.5f;
        const int i0 = (int)floorf(mu) - 4;
        float s = 0.f;
        #pragma unroll
        for (int k = 0; k < 10; k++) {
            const int i = i0 + k;
            if (i >= -PAD && i <= IMG + PAD - 1) {
                const float d = (float)i - mu;
                s += expf(-d * d * INV2S2);
            }
        }
        denom_s[tid] = s + EPSV;
    }
    __syncthreads();

    // --- build Fx (x-axis, scaled by 1/N) and Fy (y-axis) windows ---
    for (int i = tid; i < 2 * WSZ * PSZ; i += 256) {
        const int which = i / (WSZ * PSZ);     // 0 = x, 1 = y
        const int r  = i - which * (WSZ * PSZ);
        const int wl = r / PSZ;
        const int q  = r - wl * PSZ;
        const float g  = which ? gy : gx;
        const int   w0 = which ? w0y : w0x;
        const int   w  = w0 + wl;
        float val = 0.f;
        if (w >= 0 && w < IMG) {
            const float mu = g + (float)q - 7.5f;
            const float d  = (float)w - mu;
            val = expf(-d * d * INV2S2) / denom_s[which * PSZ + q];
        }
        if (which == 0) Fx_s[r] = val * (1.0f / (float)NBR);
        else            Fy_s[r] = val;
    }
    __syncthreads();

    // --- stage 1: t[c][wl][p] = sum_q Fx[wl][q] * patch[c][p][q] ---
    for (int i = tid; i < CH * WSZ * PSZ; i += 256) {
        const int c  = i / (WSZ * PSZ);
        const int r  = i - c * (WSZ * PSZ);
        const int wl = r / PSZ;
        const int p  = r - wl * PSZ;
        const float* fx = &Fx_s[wl * PSZ];
        const float* pp = &patch_s[c * (PSZ * PSZ) + p * PSZ];
        float s = 0.f;
        #pragma unroll
        for (int q = 0; q < PSZ; q++) s = fmaf(fx[q], pp[q], s);
        t_s[i] = s;
    }
    __syncthreads();

    // --- stage 2: out[b][c][h][w] += sum_p t[c][wl][p] * Fy[hl][p] ---
    for (int i = tid; i < CH * WSZ * WSZ; i += 256) {
        const int c  = i / (WSZ * WSZ);
        const int r  = i - c * (WSZ * WSZ);
        const int hl = r / WSZ;
        const int wl = r - hl * WSZ;
        const int h = w0y + hl;
        const int w = w0x + wl;
        if (h >= 0 && h < IMG && w >= 0 && w < IMG) {
            const float* tt = &t_s[(c * WSZ + wl) * PSZ];
            const float* fy = &Fy_s[hl * PSZ];
            float s = 0.f;
            #pragma unroll
            for (int p = 0; p < PSZ; p++) s = fmaf(tt[p], fy[p], s);
            atomicAdd(&out[(((size_t)b * CH + c) * IMG + h) * IMG + w], s);
        }
    }
}

extern "C" void kernel_launch(void* const* d_in, const int* in_sizes, int n_in,
                              void* d_out, int out_size) {
    const float* brushes = (const float*)d_in[0];   // [32,64,2]
    const float* patches = (const float*)d_in[1];   // [32,64,3,16,16]
    float* out = (float*)d_out;                     // [32,3,256,256]

    const int n4 = out_size / 4;
    zero_out_kernel<<<(n4 + 255) / 256, 256>>>((float4*)out, n4);

    const int B = 32;
    brush_scatter_kernel<<<B * NBR, 256>>>(brushes, patches, out);
}

// round 2
// speedup vs baseline: 1.9737x; 1.9737x over previous
#include <cuda_runtime.h>
#include <math.h>

#define IMG    256
#define PSZ    16
#define PAD    8
#define WX     28      // aligned x-window (covers the 24-px true support)
#define WY     24      // y-window
#define NBR    64
#define CH     3
#define INV2S2 12.5f   // 1/(2*sigma^2), sigma=0.2
#define EPSV   1e-7f
#define PADP   20      // patchT row pitch (floats) - conflict-free transpose/read
#define PADF   17      // filter row pitch (floats) - conflict-free broadcast
#define PITCHT 28      // tT row pitch (wl dim), multiple of 4 for LDS.128

__global__ void zero_out_kernel(float4* __restrict__ out, int n4) {
    int stride = gridDim.x * blockDim.x;
    for (int i = blockIdx.x * blockDim.x + threadIdx.x; i < n4; i += stride)
        out[i] = make_float4(0.f, 0.f, 0.f, 0.f);
}

__global__ __launch_bounds__(256) void brush_scatter_kernel(
    const float* __restrict__ brushes,   // [B, N, 2]
    const float* __restrict__ patches,   // [B, N, 3, 16, 16]
    float* __restrict__ out)             // [B, 3, 256, 256]  (h, w)
{
    __shared__ float patchT_s[CH * PSZ * PADP];  // [c][q][p], pitch 20
    __shared__ float denom_s[2 * PSZ];           // x denoms then y denoms
    __shared__ float Fx_s[WX * PADF];            // [wl][q], includes 1/N
    __shared__ float Fy_s[WY * PADF];            // [hl][p]
    __shared__ float tT_s[CH * PSZ * PITCHT];    // [c][p][wl]

    const int bn  = blockIdx.x;
    const int b   = bn / NBR;
    const int tid = threadIdx.x;

    const float gx = brushes[bn * 2 + 0] * (float)IMG;
    const float gy = brushes[bn * 2 + 1] * (float)IMG;
    const int w0x    = (int)floorf(gx) - 11;
    const int w0x_al = w0x & ~3;                // align down to 4 (works for negatives)
    const int w0y    = (int)floorf(gy) - 11;

    // --- load patch transposed: patchT[c][q][p] = patch[c][p][q] ---
    const float* pbase = patches + (size_t)bn * (CH * PSZ * PSZ);
    for (int i = tid; i < CH * PSZ * PSZ; i += 256) {
        const int c = i >> 8;
        const int r = i & 255;
        const int p = r >> 4;
        const int q = r & 15;
        patchT_s[(c * PSZ + q) * PADP + p] = pbase[i];
    }

    // --- normalization denominators over padded coord range ---
    if (tid < 2 * PSZ) {
        const int   q  = tid & (PSZ - 1);
        const float g  = (tid < PSZ) ? gx : gy;
        const float mu = g + (float)q - 7.5f;
        const int i0 = (int)floorf(mu) - 4;
        float s = 0.f;
        #pragma unroll
        for (int k = 0; k < 10; k++) {
            const int i = i0 + k;
            if (i >= -PAD && i <= IMG + PAD - 1) {
                const float d = (float)i - mu;
                s += __expf(-d * d * INV2S2);
            }
        }
        denom_s[tid] = s + EPSV;
    }
    __syncthreads();

    // --- build Fx (28x16, scaled 1/N) and Fy (24x16) windows ---
    for (int i = tid; i < (WX + WY) * PSZ; i += 256) {
        if (i < WX * PSZ) {
            const int wl = i / PSZ;
            const int q  = i - wl * PSZ;
            const int w  = w0x_al + wl;
            float val = 0.f;
            if (w >= 0 && w < IMG) {
                const float mu = gx + (float)q - 7.5f;
                const float d  = (float)w - mu;
                val = __expf(-d * d * INV2S2) / denom_s[q] * (1.0f / (float)NBR);
            }
            Fx_s[wl * PADF + q] = val;
        } else {
            const int r  = i - WX * PSZ;
            const int hl = r / PSZ;
            const int p  = r - hl * PSZ;
            const int h  = w0y + hl;
            float val = 0.f;
            if (h >= 0 && h < IMG) {
                const float mu = gy + (float)p - 7.5f;
                const float d  = (float)h - mu;
                val = __expf(-d * d * INV2S2) / denom_s[PSZ + p];
            }
            Fy_s[hl * PADF + p] = val;
        }
    }
    __syncthreads();

    // --- stage 1: tT[c][p][wl] = sum_q Fx[wl][q] * patchT[c][q][p] ---
    // thread task = (c, wl, pg): computes 4 consecutive p via float4 reads
    for (int j = tid; j < CH * WX * (PSZ / 4); j += 256) {
        const int pg = j & 3;
        const int t2 = j >> 2;
        const int wl = t2 % WX;
        const int c  = t2 / WX;
        const int p0 = pg * 4;
        const float* fx = &Fx_s[wl * PADF];
        float4 acc = make_float4(0.f, 0.f, 0.f, 0.f);
        #pragma unroll
        for (int q = 0; q < PSZ; q++) {
            const float  f = fx[q];
            const float4 v = *(const float4*)&patchT_s[(c * PSZ + q) * PADP + p0];
            acc.x = fmaf(f, v.x, acc.x);
            acc.y = fmaf(f, v.y, acc.y);
            acc.z = fmaf(f, v.z, acc.z);
            acc.w = fmaf(f, v.w, acc.w);
        }
        tT_s[(c * PSZ + p0 + 0) * PITCHT + wl] = acc.x;
        tT_s[(c * PSZ + p0 + 1) * PITCHT + wl] = acc.y;
        tT_s[(c * PSZ + p0 + 2) * PITCHT + wl] = acc.z;
        tT_s[(c * PSZ + p0 + 3) * PITCHT + wl] = acc.w;
    }
    __syncthreads();

    // --- stage 2: out[b][c][h][w0x_al+4*wlg .. +3] += sum_p tT[c][p][.] * Fy[hl][p] ---
    for (int j = tid; j < CH * WY * (WX / 4); j += 256) {
        const int wlg = j % (WX / 4);
        const int t2  = j / (WX / 4);
        const int hl  = t2 % WY;
        const int c   = t2 / WY;
        const int h   = w0y + hl;
        if (h < 0 || h >= IMG) continue;
        const int wb = w0x_al + wlg * 4;
        if (wb >= IMG || wb + 3 < 0) continue;

        const float* fy = &Fy_s[hl * PADF];
        float4 acc = make_float4(0.f, 0.f, 0.f, 0.f);
        #pragma unroll
        for (int p = 0; p < PSZ; p++) {
            const float  f = fy[p];
            const float4 v = *(const float4*)&tT_s[(c * PSZ + p) * PITCHT + wlg * 4];
            acc.x = fmaf(f, v.x, acc.x);
            acc.y = fmaf(f, v.y, acc.y);
            acc.z = fmaf(f, v.z, acc.z);
            acc.w = fmaf(f, v.w, acc.w);
        }

        float* row = out + (((size_t)b * CH + c) * IMG + h) * IMG;
        if (wb >= 0 && wb + 3 < IMG) {
            asm volatile("red.global.add.v4.f32 [%0], {%1, %2, %3, %4};"
                         :: "l"(row + wb), "f"(acc.x), "f"(acc.y), "f"(acc.z), "f"(acc.w)
                         : "memory");
        } else {
            const float comp[4] = {acc.x, acc.y, acc.z, acc.w};
            #pragma unroll
            for (int k = 0; k < 4; k++) {
                const int w = wb + k;
                if (w >= 0 && w < IMG) atomicAdd(row + w, comp[k]);
            }
        }
    }
}

extern "C" void kernel_launch(void* const* d_in, const int* in_sizes, int n_in,
                              void* d_out, int out_size) {
    const float* brushes = (const float*)d_in[0];   // [32,64,2]
    const float* patches = (const float*)d_in[1];   // [32,64,3,16,16]
    float* out = (float*)d_out;                     // [32,3,256,256]

    const int n4 = out_size / 4;
    zero_out_kernel<<<(n4 + 255) / 256, 256>>>((float4*)out, n4);

    brush_scatter_kernel<<<32 * NBR, 256>>>(brushes, patches, out);
}

// round 3
// speedup vs baseline: 2.0603x; 1.0439x over previous
#include <cuda_runtime.h>
#include <math.h>

#define IMG    256
#define PSZ    16
#define PAD    8
#define WX     28      // aligned x-window (covers 24-px true support)
#define WY     24      // y-window
#define NBR    64
#define CH     3
#define INV2S2 12.5f
#define EPSV   1e-7f
#define PADP   20      // patchT row pitch [c][q][p]
#define PFX    28      // FxT row pitch   [q][wl]
#define PFY    24      // FyT row pitch   [p][hl]
#define PT     28      // tT row pitch    [c][p][wl]

__global__ void zero_out_kernel(float4* __restrict__ out, int n4) {
    int stride = gridDim.x * blockDim.x;
    for (int i = blockIdx.x * blockDim.x + threadIdx.x; i < n4; i += stride)
        out[i] = make_float4(0.f, 0.f, 0.f, 0.f);
}

__global__ __launch_bounds__(256) void brush_scatter_kernel(
    const float* __restrict__ brushes,   // [B, N, 2]
    const float* __restrict__ patches,   // [B, N, 3, 16, 16]
    float* __restrict__ out)             // [B, 3, 256, 256]
{
    __shared__ __align__(16) float patchT_s[2][CH * PSZ * PADP]; // [c][q][p]
    __shared__ __align__(16) float denom_s[2][2 * PSZ];
    __shared__ __align__(16) float FxT_s[2][PSZ * PFX];          // [q][wl], incl 1/N
    __shared__ __align__(16) float FyT_s[2][PSZ * PFY];          // [p][hl]
    __shared__ __align__(16) float tT_s[2][CH * PSZ * PT];       // [c][p][wl]
    __shared__ float g_s[2][2];   // gx, gy
    __shared__ int   w0_s[2][2];  // w0x_al, w0y

    const int bn0 = blockIdx.x * 2;
    const int b   = bn0 >> 6;
    const int tid = threadIdx.x;

    // ---- phase A: patch loads (transposed), brush params, denominators ----
    if (tid < 2) {
        const float gx = brushes[(bn0 + tid) * 2 + 0] * (float)IMG;
        const float gy = brushes[(bn0 + tid) * 2 + 1] * (float)IMG;
        g_s[tid][0] = gx;  g_s[tid][1] = gy;
        w0_s[tid][0] = ((int)floorf(gx) - 11) & ~3;
        w0_s[tid][1] = (int)floorf(gy) - 11;
    }
    // denominators: 64 threads (slot, axis, q)
    if (tid >= 64 && tid < 128) {
        const int t    = tid - 64;
        const int slot = t >> 5;
        const int ax   = (t >> 4) & 1;
        const int q    = t & 15;
        const float g  = brushes[(bn0 + slot) * 2 + ax] * (float)IMG;
        const float mu = g + (float)q - 7.5f;
        const int i0 = (int)floorf(mu) - 4;
        float s = 0.f;
        #pragma unroll
        for (int k = 0; k < 10; k++) {
            const int i = i0 + k;
            if (i >= -PAD && i <= IMG + PAD - 1) {
                const float d = (float)i - mu;
                s += __expf(-d * d * INV2S2);
            }
        }
        denom_s[slot][ax * PSZ + q] = s + EPSV;
    }
    // patch transpose loads: 1536 elems, 6 per thread
    {
        const float* pbase = patches + (size_t)bn0 * (CH * PSZ * PSZ);
        #pragma unroll
        for (int it = 0; it < 6; it++) {
            const int i = tid + it * 256;          // [slot][c][p][q]
            const int slot = i >> 8 >= 3 ? 1 : 0;
            const int r = i - slot * 768;
            const int c = r >> 8;
            const int p = (r >> 4) & 15;
            const int q = r & 15;
            patchT_s[slot][(c * PSZ + q) * PADP + p] = pbase[i];
        }
    }
    __syncthreads();

    // ---- phase B: build FxT [q][wl] (incl 1/N) and FyT [p][hl] ----
    // per slot: 448 fx elems + 384 fy elems = 832; total 1664 -> 6.5/thread
    for (int i = tid; i < 2 * 832; i += 256) {
        const int slot = i >= 832;
        const int r = i - slot * 832;
        if (r < PSZ * WX) {
            const int q  = r / WX;
            const int wl = r - q * WX;
            const int w  = w0_s[slot][0] + wl;
            float val = 0.f;
            if (w >= 0 && w < IMG) {
                const float mu = g_s[slot][0] + (float)q - 7.5f;
                const float d  = (float)w - mu;
                val = __expf(-d * d * INV2S2) / denom_s[slot][q] * (1.0f / (float)NBR);
            }
            FxT_s[slot][q * PFX + wl] = val;
        } else {
            const int rr = r - PSZ * WX;
            const int p  = rr / WY;
            const int hl = rr - p * WY;
            const int h  = w0_s[slot][1] + hl;
            float val = 0.f;
            if (h >= 0 && h < IMG) {
                const float mu = g_s[slot][1] + (float)p - 7.5f;
                const float d  = (float)h - mu;
                val = __expf(-d * d * INV2S2) / denom_s[slot][PSZ + p];
            }
            FyT_s[slot][p * PFY + hl] = val;
        }
    }
    __syncthreads();

    // ---- stage 1: tT[c][p][wl] = sum_q FxT[q][wl] * patchT[c][q][p] ----
    // task = (slot, c, pg, wlq): 2*3*4*7 = 168 tasks, 4wl x 4p block each
    if (tid < 168) {
        const int wlq = tid % 7;
        int u = tid / 7;
        const int pg = u & 3;  u >>= 2;
        const int c  = u % 3;
        const int slot = u / 3;
        const int p0  = pg * 4;
        const int wl0 = wlq * 4;

        float acc[4][4] = {};   // [wl][p]
        #pragma unroll
        for (int q = 0; q < PSZ; q++) {
            const float4 fx = *(const float4*)&FxT_s[slot][q * PFX + wl0];
            const float4 pv = *(const float4*)&patchT_s[slot][(c * PSZ + q) * PADP + p0];
            const float fxa[4] = {fx.x, fx.y, fx.z, fx.w};
            const float pva[4] = {pv.x, pv.y, pv.z, pv.w};
            #pragma unroll
            for (int i = 0; i < 4; i++)
                #pragma unroll
                for (int pp = 0; pp < 4; pp++)
                    acc[i][pp] = fmaf(fxa[i], pva[pp], acc[i][pp]);
        }
        #pragma unroll
        for (int pp = 0; pp < 4; pp++) {
            float4 o = make_float4(acc[0][pp], acc[1][pp], acc[2][pp], acc[3][pp]);
            *(float4*)&tT_s[slot][(c * PSZ + p0 + pp) * PT + wl0] = o;
        }
    }
    __syncthreads();

    // ---- stage 2: out[h][w] block = sum_p tT[c][p][wl] * FyT[p][hl] ----
    // task = (slot, c, hlg, wlq): 2*3*6*7 = 252 tasks, 4h x 4w block each
    if (tid < 252) {
        const int wlq = tid % 7;
        int u = tid / 7;
        const int hlg = u % 6;  u /= 6;
        const int c   = u % 3;
        const int slot = u / 3;
        const int wl0 = wlq * 4;
        const int hl0 = hlg * 4;

        float acc[4][4] = {};   // [hl][wl]
        #pragma unroll
        for (int p = 0; p < PSZ; p++) {
            const float4 tv = *(const float4*)&tT_s[slot][(c * PSZ + p) * PT + wl0];
            const float4 fy = *(const float4*)&FyT_s[slot][p * PFY + hl0];
            const float fya[4] = {fy.x, fy.y, fy.z, fy.w};
            const float tva[4] = {tv.x, tv.y, tv.z, tv.w};
            #pragma unroll
            for (int i = 0; i < 4; i++)
                #pragma unroll
                for (int k = 0; k < 4; k++)
                    acc[i][k] = fmaf(fya[i], tva[k], acc[i][k]);
        }

        const int wb = w0_s[slot][0] + wl0;
        const int hb = w0_s[slot][1] + hl0;
        float* base = out + ((size_t)b * CH + c) * (IMG * IMG);
        const bool wok = (wb >= 0) && (wb + 3 < IMG);
        #pragma unroll
        for (int i = 0; i < 4; i++) {
            const int h = hb + i;
            if (h < 0 || h >= IMG) continue;
            float* row = base + (size_t)h * IMG;
            if (wok) {
                asm volatile("red.global.add.v4.f32 [%0], {%1, %2, %3, %4};"
                             :: "l"(row + wb), "f"(acc[i][0]), "f"(acc[i][1]),
                                "f"(acc[i][2]), "f"(acc[i][3])
                             : "memory");
            } else {
                #pragma unroll
                for (int k = 0; k < 4; k++) {
                    const int w = wb + k;
                    if (w >= 0 && w < IMG) atomicAdd(row + w, acc[i][k]);
                }
            }
        }
    }
}

extern "C" void kernel_launch(void* const* d_in, const int* in_sizes, int n_in,
                              void* d_out, int out_size) {
    const float* brushes = (const float*)d_in[0];   // [32,64,2]
    const float* patches = (const float*)d_in[1];   // [32,64,3,16,16]
    float* out = (float*)d_out;                     // [32,3,256,256]

    const int n4 = out_size / 4;
    zero_out_kernel<<<(n4 + 255) / 256, 256>>>((float4*)out, n4);

    brush_scatter_kernel<<<32 * NBR / 2, 256>>>(brushes, patches, out);
}